// round 13
// baseline (speedup 1.0000x reference)
#include <cuda_runtime.h>
#include <cstdint>

// SparseConv3d as implicit GEMM via mma.sync tf32 m16n8k8.
// R12 + chunked raw-f32 fill (HW tf32 truncation on A; B pre-rounded RN).

#define NV      96
#define NV2     (NV*NV)
#define CI_     32
#define CO_     64
#define ROWW    98
#define PLANE_Q (NV*ROWW)        // 9408
#define MT      128
#define NTILES  74               // ceil(9408/128)
#define S_STR   328              // mod 32 == 8 -> conflict-free A frags; mod 4 == 0
#define S_ROWS  326
#define EP_STR  66

// weight fragments: [tap][gnt(8)][ks(4)][lane(32)] float2  (lane-fastest)
__device__ float2 g_wfrag[27 * 8 * 4 * 32];

__device__ __forceinline__ uint32_t f2tf32(float f) {
    uint32_t r; asm("cvt.rna.tf32.f32 %0, %1;" : "=r"(r) : "f"(f)); return r;
}

extern "C" __global__ void wprep_kernel(const float* __restrict__ wgt) {
    int idx = blockIdx.x * 256 + threadIdx.x;   // over 27*8*4*32 float2
    if (idx >= 27 * 8 * 4 * 32) return;
    int lane = idx & 31;
    int r    = idx >> 5;
    int ks   = r & 3;  r >>= 2;
    int gnt  = r & 7;  r >>= 3;
    int tap  = r;
    int g = lane >> 2, t = lane & 3;
    int co  = gnt * 8 + g;
    int ci0 = ks * 8 + t;
    float2 v;
    v.x = __uint_as_float(f2tf32(wgt[(co * CI_ + ci0)     * 27 + tap]));
    v.y = __uint_as_float(f2tf32(wgt[(co * CI_ + ci0 + 4) * 27 + tap]));
    g_wfrag[idx] = v;
}

extern "C" __global__ void __launch_bounds__(256, 4)
conv_mma_kernel(const float* __restrict__ x, const int* __restrict__ mask,
                const float* __restrict__ bias, float* __restrict__ out)
{
    __shared__ float scratch[CI_ * S_STR];   // reused as epilogue [128][66]
    __shared__ float bs[CO_];

    const int tid  = threadIdx.x;
    const int w    = tid >> 5;
    const int lane = tid & 31;
    const int g    = lane >> 2;
    const int t    = lane & 3;

    const int pz = blockIdx.y;               // b*96 + d
    const int b = pz / NV, d = pz % NV;
    const int q0   = blockIdx.x * MT;
    const int q_lo = q0 - 99;

    const int warp_m = (w >> 1) * 32;        // 0,32,64,96
    const int warp_n = (w & 1) * 32;         // 0,32

    if (tid < CO_) bs[tid] = bias[tid];

    float acc[2][4][4];
    #pragma unroll
    for (int mt = 0; mt < 2; mt++)
        #pragma unroll
        for (int nt = 0; nt < 4; nt++)
            #pragma unroll
            for (int c = 0; c < 4; c++) acc[mt][nt][c] = 0.0f;

    const uint32_t* scr_u = (const uint32_t*)scratch;
    const float2* wbase = g_wfrag + (size_t)(w & 1) * 4 * 128 + lane;

    // fill decomposition: ci = tid>>3 (8 threads per ci), thread covers 44 s
    const int fill_ci = tid >> 3;
    const int fill_s0 = (tid & 7) * 44;
    const int fill_s1 = (fill_s0 + 44 < S_ROWS) ? fill_s0 + 44 : S_ROWS;

    for (int dz = 0; dz < 3; dz++) {
        const int dcur = d + dz - 1;
        const bool dok = ((unsigned)dcur < (unsigned)NV);
        __syncthreads();   // all warps done reading previous dz's scratch

        // ---- chunked fill: raw f32 (no cvt), 4-wide fast path ----
        {
            const float* xp = x + ((size_t)(b * CI_ + fill_ci) * NV + (dok ? dcur : 0)) * NV2;
            float* sp = scratch + fill_ci * S_STR;
            int s  = fill_s0;
            int qg = q_lo + s;
            int hh = (qg + 196) / 98 - 2;        // one exact floor-div per plane
            int ww = qg - hh * ROWW;
            #pragma unroll 1
            for (; s < fill_s1; s += 4) {
                if (dok && (unsigned)hh < (unsigned)NV && ww <= NV - 4 && s + 4 <= fill_s1) {
                    const float* rp = xp + hh * NV + ww;
                    float4 v = make_float4(rp[0], rp[1], rp[2], rp[3]);
                    *(float4*)(sp + s) = v;
                } else {
                    #pragma unroll
                    for (int e = 0; e < 4; e++) {
                        if (s + e < fill_s1) {
                            int w2 = ww + e, h2 = hh;
                            if (w2 >= ROWW) { w2 -= ROWW; h2++; }
                            float v = 0.0f;
                            if (dok && (unsigned)h2 < (unsigned)NV && w2 < NV)
                                v = xp[h2 * NV + w2];
                            sp[s + e] = v;
                        }
                    }
                }
                ww += 4;
                if (ww >= ROWW) { ww -= ROWW; hh++; }
            }
        }
        __syncthreads();

        #pragma unroll 1
        for (int kh = 0; kh < 3; kh++) {
            #pragma unroll 1
            for (int kw = 0; kw < 3; kw++) {
                const int tap   = dz * 9 + kh * 3 + kw;
                const int sbase = 99 + (kh - 1) * ROWW + (kw - 1) + warp_m + g;
                const float2* wf = wbase + (size_t)tap * 1024;
                const uint32_t* ap = scr_u + (size_t)t * S_STR + sbase;

                #pragma unroll
                for (int ks = 0; ks < 4; ks++) {
                    float2 bf0 = wf[(0 * 4 + ks) * 32];
                    float2 bf1 = wf[(1 * 4 + ks) * 32];
                    float2 bf2 = wf[(2 * 4 + ks) * 32];
                    float2 bf3 = wf[(3 * 4 + ks) * 32];

                    const uint32_t* a_ks = ap + (size_t)(ks * 8) * S_STR;
                    #pragma unroll
                    for (int mt = 0; mt < 2; mt++) {
                        const uint32_t* am = a_ks + mt * 16;
                        uint32_t a0 = am[0];
                        uint32_t a1 = am[8];
                        uint32_t a2 = am[4 * S_STR];
                        uint32_t a3 = am[4 * S_STR + 8];
                        #pragma unroll
                        for (int nt = 0; nt < 4; nt++) {
                            float2 bv = (nt == 0) ? bf0 : (nt == 1) ? bf1 : (nt == 2) ? bf2 : bf3;
                            asm volatile(
                                "mma.sync.aligned.m16n8k8.row.col.f32.tf32.tf32.f32 "
                                "{%0,%1,%2,%3}, {%4,%5,%6,%7}, {%8,%9}, {%0,%1,%2,%3};\n"
                                : "+f"(acc[mt][nt][0]), "+f"(acc[mt][nt][1]),
                                  "+f"(acc[mt][nt][2]), "+f"(acc[mt][nt][3])
                                : "r"(a0), "r"(a1), "r"(a2), "r"(a3),
                                  "r"(__float_as_uint(bv.x)),
                                  "r"(__float_as_uint(bv.y)));
                        }
                    }
                }
            }
        }
    }

    // ---- epilogue: acc -> smem transpose -> coalesced masked stores ----
    __syncthreads();
    float* ep = scratch;             // [128][66]
    #pragma unroll
    for (int mt = 0; mt < 2; mt++) {
        #pragma unroll
        for (int nt = 0; nt < 4; nt++) {
            int m  = warp_m + mt * 16 + g;
            int co = warp_n + nt * 8 + 2 * t;
            *(float2*)(ep + m * EP_STR + co)       = make_float2(acc[mt][nt][0], acc[mt][nt][1]);
            *(float2*)(ep + (m + 8) * EP_STR + co) = make_float2(acc[mt][nt][2], acc[mt][nt][3]);
        }
    }
    __syncthreads();

    #pragma unroll
    for (int it = 0; it < 4; it++) {
        int m  = it * 32 + lane;
        int q  = q0 + m;
        int hh = q / ROWW;
        int ww = q - hh * ROWW;
        bool ok = (q < PLANE_Q) && (ww < NV);
        float mval = 0.0f;
        int sp = hh * NV + ww;
        if (ok) mval = (float)mask[(size_t)pz * NV2 + sp];
        #pragma unroll
        for (int j = 0; j < 8; j++) {
            int co = w * 8 + j;
            if (ok)
                out[((size_t)(b * CO_ + co) * NV + d) * NV2 + sp] =
                    (ep[m * EP_STR + co] + bs[co]) * mval;
        }
    }
}

extern "C" void kernel_launch(void* const* d_in, const int* in_sizes, int n_in,
                              void* d_out, int out_size)
{
    const float* x    = (const float*)d_in[0];
    const int*   mask = (const int*)  d_in[1];
    const float* wgt  = (const float*)d_in[2];
    const float* bias = (const float*)d_in[3];
    float* out = (float*)d_out;

    wprep_kernel<<<(27 * 8 * 4 * 32 + 255) / 256, 256>>>(wgt);

    dim3 grid(NTILES, 2 * NV);   // (74, 192)
    conv_mma_kernel<<<grid, 256>>>(x, mask, bias, out);
}

// round 14
// speedup vs baseline: 1.2251x; 1.2251x over previous
#include <cuda_runtime.h>
#include <cstdint>

// SparseConv3d as implicit GEMM via mma.sync tf32 m16n8k8.
// R12 mainloop + raw-f32 interleaved fill (no cvt) + MT=256 / 512 thr / 2 CTAs/SM.

#define NV      96
#define NV2     (NV*NV)
#define CI_     32
#define CO_     64
#define ROWW    98
#define PLANE_Q (NV*ROWW)        // 9408
#define MT      256
#define NTILES  37               // ceil(9408/256)
#define S_STR   456              // mod 32 == 8 -> conflict-free A frags
#define S_ROWS  454
#define EP_STR  66

// weight fragments: [tap][gnt(8)][ks(4)][lane(32)] float2  (lane-fastest)
__device__ float2 g_wfrag[27 * 8 * 4 * 32];

__device__ __forceinline__ uint32_t f2tf32(float f) {
    uint32_t r; asm("cvt.rna.tf32.f32 %0, %1;" : "=r"(r) : "f"(f)); return r;
}

extern "C" __global__ void wprep_kernel(const float* __restrict__ wgt) {
    int idx = blockIdx.x * 256 + threadIdx.x;   // over 27*8*4*32 float2
    if (idx >= 27 * 8 * 4 * 32) return;
    int lane = idx & 31;
    int r    = idx >> 5;
    int ks   = r & 3;  r >>= 2;
    int gnt  = r & 7;  r >>= 3;
    int tap  = r;
    int g = lane >> 2, t = lane & 3;
    int co  = gnt * 8 + g;
    int ci0 = ks * 8 + t;
    float2 v;
    v.x = __uint_as_float(f2tf32(wgt[(co * CI_ + ci0)     * 27 + tap]));
    v.y = __uint_as_float(f2tf32(wgt[(co * CI_ + ci0 + 4) * 27 + tap]));
    g_wfrag[idx] = v;
}

extern "C" __global__ void __launch_bounds__(512, 2)
conv_mma_kernel(const float* __restrict__ x, const int* __restrict__ mask,
                const float* __restrict__ bias, float* __restrict__ out)
{
    __shared__ float scratch[CI_ * S_STR];   // 58368 B; reused as epilogue [128][66]
    __shared__ float bs[CO_];

    const int tid  = threadIdx.x;
    const int w    = tid >> 5;               // 0..15
    const int lane = tid & 31;
    const int g    = lane >> 2;
    const int t    = lane & 3;

    const int pz = blockIdx.y;               // b*96 + d
    const int b = pz / NV, d = pz % NV;
    const int q0   = blockIdx.x * MT;
    const int q_lo = q0 - 99;

    const int warp_m = (w >> 1) * 32;        // 0..224
    const int warp_n = (w & 1) * 32;         // 0,32

    if (tid < CO_) bs[tid] = bias[tid];

    float acc[2][4][4];
    #pragma unroll
    for (int mt = 0; mt < 2; mt++)
        #pragma unroll
        for (int nt = 0; nt < 4; nt++)
            #pragma unroll
            for (int c = 0; c < 4; c++) acc[mt][nt][c] = 0.0f;

    const uint32_t* scr_u = (const uint32_t*)scratch;
    const float2* wbase = g_wfrag + (size_t)(w & 1) * 4 * 128 + lane;

    for (int dz = 0; dz < 3; dz++) {
        const int dcur = d + dz - 1;
        const bool dok = ((unsigned)dcur < (unsigned)NV);
        __syncthreads();   // all warps done reading previous dz's scratch

        // ---- interleaved raw-f32 fill: ci = tid>>4, s walks (tid&15)+16j ----
        {
            const int ci = tid >> 4;
            int s  = tid & 15;
            int qg = q_lo + s;
            int hh = (qg + 196) / 98 - 2;        // one exact floor-div per plane
            int ww = qg - hh * ROWW;
            const float* xp = x + ((size_t)(b * CI_ + ci) * NV + (dok ? dcur : 0)) * NV2;
            float* sp = scratch + ci * S_STR;
            #pragma unroll 1
            for (; s < S_ROWS; s += 16) {
                float v = 0.0f;
                if (dok && (unsigned)hh < (unsigned)NV && ww < NV)
                    v = xp[hh * NV + ww];
                sp[s] = v;                        // raw f32; HW mma truncates to tf32
                ww += 16;
                if (ww >= ROWW) { ww -= ROWW; hh++; }
            }
        }
        __syncthreads();

        #pragma unroll 1
        for (int kh = 0; kh < 3; kh++) {
            #pragma unroll 1
            for (int kw = 0; kw < 3; kw++) {
                const int tap   = dz * 9 + kh * 3 + kw;
                const int sbase = 99 + (kh - 1) * ROWW + (kw - 1) + warp_m + g;
                const float2* wf = wbase + (size_t)tap * 1024;
                const uint32_t* ap = scr_u + (size_t)t * S_STR + sbase;

                #pragma unroll
                for (int ks = 0; ks < 4; ks++) {
                    float2 bf0 = wf[(0 * 4 + ks) * 32];
                    float2 bf1 = wf[(1 * 4 + ks) * 32];
                    float2 bf2 = wf[(2 * 4 + ks) * 32];
                    float2 bf3 = wf[(3 * 4 + ks) * 32];

                    const uint32_t* a_ks = ap + (size_t)(ks * 8) * S_STR;
                    #pragma unroll
                    for (int mt = 0; mt < 2; mt++) {
                        const uint32_t* am = a_ks + mt * 16;
                        uint32_t a0 = am[0];
                        uint32_t a1 = am[8];
                        uint32_t a2 = am[4 * S_STR];
                        uint32_t a3 = am[4 * S_STR + 8];
                        #pragma unroll
                        for (int nt = 0; nt < 4; nt++) {
                            float2 bv = (nt == 0) ? bf0 : (nt == 1) ? bf1 : (nt == 2) ? bf2 : bf3;
                            asm volatile(
                                "mma.sync.aligned.m16n8k8.row.col.f32.tf32.tf32.f32 "
                                "{%0,%1,%2,%3}, {%4,%5,%6,%7}, {%8,%9}, {%0,%1,%2,%3};\n"
                                : "+f"(acc[mt][nt][0]), "+f"(acc[mt][nt][1]),
                                  "+f"(acc[mt][nt][2]), "+f"(acc[mt][nt][3])
                                : "r"(a0), "r"(a1), "r"(a2), "r"(a3),
                                  "r"(__float_as_uint(bv.x)),
                                  "r"(__float_as_uint(bv.y)));
                        }
                    }
                }
            }
        }
    }

    // ---- epilogue: two 128-row passes via smem transpose, coalesced stores ----
    float* ep = scratch;   // [128][66]
    #pragma unroll 1
    for (int pass = 0; pass < 2; pass++) {
        __syncthreads();
        if ((w >> 3) == pass) {
            const int m_loc = (warp_m & 127);
            #pragma unroll
            for (int mt = 0; mt < 2; mt++) {
                #pragma unroll
                for (int nt = 0; nt < 4; nt++) {
                    int m  = m_loc + mt * 16 + g;
                    int co = warp_n + nt * 8 + 2 * t;
                    *(float2*)(ep + m * EP_STR + co) =
                        make_float2(acc[mt][nt][0], acc[mt][nt][1]);
                    *(float2*)(ep + (m + 8) * EP_STR + co) =
                        make_float2(acc[mt][nt][2], acc[mt][nt][3]);
                }
            }
        }
        __syncthreads();

        const int mg0 = pass * 128;
        #pragma unroll
        for (int it = 0; it < 4; it++) {
            int m  = it * 32 + lane;
            int q  = q0 + mg0 + m;
            int hh = q / ROWW;
            int ww = q - hh * ROWW;
            bool ok = (q < PLANE_Q) && (ww < NV);
            int sp  = hh * NV + ww;
            float mval = 0.0f;
            if (ok) mval = (float)mask[(size_t)pz * NV2 + sp];
            #pragma unroll
            for (int j = 0; j < 4; j++) {
                int co = w * 4 + j;
                if (ok)
                    out[((size_t)(b * CO_ + co) * NV + d) * NV2 + sp] =
                        (ep[m * EP_STR + co] + bs[co]) * mval;
            }
        }
    }
}

extern "C" void kernel_launch(void* const* d_in, const int* in_sizes, int n_in,
                              void* d_out, int out_size)
{
    const float* x    = (const float*)d_in[0];
    const int*   mask = (const int*)  d_in[1];
    const float* wgt  = (const float*)d_in[2];
    const float* bias = (const float*)d_in[3];
    float* out = (float*)d_out;

    wprep_kernel<<<(27 * 8 * 4 * 32 + 255) / 256, 256>>>(wgt);

    dim3 grid(NTILES, 2 * NV);   // (37, 192)
    conv_mma_kernel<<<grid, 512>>>(x, mask, bias, out);
}

// round 15
// speedup vs baseline: 1.9479x; 1.5900x over previous
#include <cuda_runtime.h>
#include <cuda_fp16.h>
#include <cstdint>

// SparseConv3d as implicit GEMM via mma.sync fp16 m16n8k16 (fp32 accumulate).
// fp16 mantissa == tf32 mantissa (10 bits) -> same precision class, 2x MACs/instr.
// CTA: M=256 spatial x N=64 co, 512 threads, 2 CTAs/SM.

#define NV      96
#define NV2     (NV*NV)
#define NV3     (NV*NV2)
#define CI_     32
#define CO_     64
#define ROWW    98
#define PLANE_Q (NV*ROWW)        // 9408
#define MT      256
#define NTILES  37               // ceil(9408/256)
#define S_STR   456              // mod 32 == 8 -> conflict-free A frags
#define S_ROWS  454
#define KP      16               // ci pairs
#define EP_STR  66

// B fragments: [tap][gnt(8)][ks2(2)][lane(32)] float2 = {b0(half2), b1(half2)}
__device__ float2 g_wfrag[27 * 8 * 2 * 32];

extern "C" __global__ void wprep_kernel(const float* __restrict__ wgt) {
    int idx = blockIdx.x * 256 + threadIdx.x;   // over 27*8*2*32
    if (idx >= 27 * 8 * 2 * 32) return;
    int lane = idx & 31;
    int r    = idx >> 5;
    int ks2  = r & 1;  r >>= 1;
    int gnt  = r & 7;  r >>= 3;
    int tap  = r;
    int g = lane >> 2, t = lane & 3;
    int co = gnt * 8 + g;
    int c0 = ks2 * 16 + 2 * t;          // b0: k = 2t, 2t+1
    int c1 = c0 + 8;                     // b1: k = 8+2t, 8+2t+1
    __half2 b0 = __floats2half2_rn(wgt[(co * CI_ + c0)     * 27 + tap],
                                   wgt[(co * CI_ + c0 + 1) * 27 + tap]);
    __half2 b1 = __floats2half2_rn(wgt[(co * CI_ + c1)     * 27 + tap],
                                   wgt[(co * CI_ + c1 + 1) * 27 + tap]);
    float2 v;
    v.x = __uint_as_float(*(uint32_t*)&b0);
    v.y = __uint_as_float(*(uint32_t*)&b1);
    g_wfrag[idx] = v;
}

extern "C" __global__ void __launch_bounds__(512, 2)
conv_mma_kernel(const float* __restrict__ x, const int* __restrict__ mask,
                const float* __restrict__ bias, float* __restrict__ out)
{
    // scratch as half2 grid [KP][S_STR]; epilogue reuses as float [128][66]
    __shared__ float smem_f[128 * EP_STR];   // 33792 floats >= KP*S_STR uint32 (7296)
    __shared__ float bs[CO_];
    uint32_t* scratch = (uint32_t*)smem_f;

    const int tid  = threadIdx.x;
    const int w    = tid >> 5;               // 0..15
    const int lane = tid & 31;
    const int g    = lane >> 2;
    const int t    = lane & 3;

    const int pz = blockIdx.y;               // b*96 + d
    const int b = pz / NV, d = pz % NV;
    const int q0   = blockIdx.x * MT;
    const int q_lo = q0 - 99;

    const int warp_m = (w >> 1) * 32;        // 0..224
    const int warp_n = (w & 1) * 32;         // 0,32

    if (tid < CO_) bs[tid] = bias[tid];

    float acc[2][4][4];
    #pragma unroll
    for (int mt = 0; mt < 2; mt++)
        #pragma unroll
        for (int nt = 0; nt < 4; nt++)
            #pragma unroll
            for (int c = 0; c < 4; c++) acc[mt][nt][c] = 0.0f;

    const float2* wbase = g_wfrag + (size_t)(w & 1) * 4 * 64 + lane;  // gnt-half offset: 4*2*32

    for (int dz = 0; dz < 3; dz++) {
        const int dcur = d + dz - 1;
        const bool dok = ((unsigned)dcur < (unsigned)NV);
        __syncthreads();   // all warps done reading previous dz's scratch

        // ---- fill: kp = tid>>5 (32 threads/kp), s walks (tid&31)+32j, half2 pack ----
        {
            const int kp = tid >> 5;
            int s  = tid & 31;
            int qg = q_lo + s;
            int hh = (qg + 196) / 98 - 2;        // one exact floor-div per plane
            int ww = qg - hh * ROWW;
            const float* xp0 = x + ((size_t)(b * CI_ + 2 * kp) * NV + (dok ? dcur : 0)) * NV2;
            const float* xp1 = xp0 + NV3;
            uint32_t* sp = scratch + kp * S_STR;
            #pragma unroll 1
            for (; s < S_ROWS; s += 32) {
                float v0 = 0.0f, v1 = 0.0f;
                if (dok && (unsigned)hh < (unsigned)NV && ww < NV) {
                    int o = hh * NV + ww;
                    v0 = xp0[o]; v1 = xp1[o];
                }
                __half2 h = __floats2half2_rn(v0, v1);
                sp[s] = *(uint32_t*)&h;
                ww += 32;
                if (ww >= ROWW) { ww -= ROWW; hh++; }
            }
        }
        __syncthreads();

        #pragma unroll 1
        for (int kh = 0; kh < 3; kh++) {
            #pragma unroll 1
            for (int kw = 0; kw < 3; kw++) {
                const int tap   = dz * 9 + kh * 3 + kw;
                const int sbase = 99 + (kh - 1) * ROWW + (kw - 1) + warp_m + g;
                const float2* wf = wbase + (size_t)tap * 512;   // 8*2*32
                const uint32_t* ap = scratch + (size_t)t * S_STR + sbase;

                #pragma unroll
                for (int ks2 = 0; ks2 < 2; ks2++) {
                    // B: 4 lane-fastest LDG.64 = {b0,b1} per nt
                    float2 bf0 = wf[(0 * 2 + ks2) * 32];
                    float2 bf1 = wf[(1 * 2 + ks2) * 32];
                    float2 bf2 = wf[(2 * 2 + ks2) * 32];
                    float2 bf3 = wf[(3 * 2 + ks2) * 32];

                    const uint32_t* a_ks = ap + (size_t)(ks2 * 8) * S_STR;
                    #pragma unroll
                    for (int mt = 0; mt < 2; mt++) {
                        const uint32_t* am = a_ks + mt * 16;
                        uint32_t a0 = am[0];
                        uint32_t a1 = am[8];
                        uint32_t a2 = am[4 * S_STR];
                        uint32_t a3 = am[4 * S_STR + 8];
                        #pragma unroll
                        for (int nt = 0; nt < 4; nt++) {
                            float2 bv = (nt == 0) ? bf0 : (nt == 1) ? bf1 : (nt == 2) ? bf2 : bf3;
                            asm volatile(
                                "mma.sync.aligned.m16n8k16.row.col.f32.f16.f16.f32 "
                                "{%0,%1,%2,%3}, {%4,%5,%6,%7}, {%8,%9}, {%0,%1,%2,%3};\n"
                                : "+f"(acc[mt][nt][0]), "+f"(acc[mt][nt][1]),
                                  "+f"(acc[mt][nt][2]), "+f"(acc[mt][nt][3])
                                : "r"(a0), "r"(a1), "r"(a2), "r"(a3),
                                  "r"(__float_as_uint(bv.x)),
                                  "r"(__float_as_uint(bv.y)));
                        }
                    }
                }
            }
        }
    }

    // ---- epilogue: two 128-row passes via smem transpose, coalesced stores ----
    float* ep = smem_f;   // [128][66]
    #pragma unroll 1
    for (int pass = 0; pass < 2; pass++) {
        __syncthreads();
        if ((w >> 3) == pass) {
            const int m_loc = (warp_m & 127);
            #pragma unroll
            for (int mt = 0; mt < 2; mt++) {
                #pragma unroll
                for (int nt = 0; nt < 4; nt++) {
                    int m  = m_loc + mt * 16 + g;
                    int co = warp_n + nt * 8 + 2 * t;
                    *(float2*)(ep + m * EP_STR + co) =
                        make_float2(acc[mt][nt][0], acc[mt][nt][1]);
                    *(float2*)(ep + (m + 8) * EP_STR + co) =
                        make_float2(acc[mt][nt][2], acc[mt][nt][3]);
                }
            }
        }
        __syncthreads();

        const int mg0 = pass * 128;
        #pragma unroll
        for (int it = 0; it < 4; it++) {
            int m  = it * 32 + lane;
            int q  = q0 + mg0 + m;
            int hh = q / ROWW;
            int ww = q - hh * ROWW;
            bool ok = (q < PLANE_Q) && (ww < NV);
            int sp  = hh * NV + ww;
            float mval = 0.0f;
            if (ok) mval = (float)mask[(size_t)pz * NV2 + sp];
            #pragma unroll
            for (int j = 0; j < 4; j++) {
                int co = w * 4 + j;
                if (ok)
                    out[((size_t)(b * CO_ + co) * NV + d) * NV2 + sp] =
                        (ep[m * EP_STR + co] + bs[co]) * mval;
            }
        }
    }
}

extern "C" void kernel_launch(void* const* d_in, const int* in_sizes, int n_in,
                              void* d_out, int out_size)
{
    const float* x    = (const float*)d_in[0];
    const int*   mask = (const int*)  d_in[1];
    const float* wgt  = (const float*)d_in[2];
    const float* bias = (const float*)d_in[3];
    float* out = (float*)d_out;

    wprep_kernel<<<(27 * 8 * 2 * 32 + 255) / 256, 256>>>(wgt);

    dim3 grid(NTILES, 2 * NV);   // (37, 192)
    conv_mma_kernel<<<grid, 512>>>(x, mask, bias, out);
}

// round 16
// speedup vs baseline: 2.0100x; 1.0319x over previous
#include <cuda_runtime.h>
#include <cuda_fp16.h>
#include <cstdint>

// SparseConv3d as implicit GEMM via mma.sync fp16 m16n8k16 + ldmatrix A loads.
// Scratch transposed to [s][kp] (stride 20 words) so ldmatrix rows are contiguous.

#define NV      96
#define NV2     (NV*NV)
#define NV3     (NV*NV2)
#define CI_     32
#define CO_     64
#define ROWW    98
#define PLANE_Q (NV*ROWW)        // 9408
#define MT      256
#define NTILES  37
#define S_ROWS  454
#define S_W     20               // words per s-row (16 kp + 4 pad) -> LDSM conflict-free
#define EP_STR  66
#define SCR_WORDS (S_ROWS*S_W)   // 9080 >= 128*66 epilogue floats

// B fragments: [tap][gnt(8)][ks2(2)][lane(32)] float2 = {b0(half2), b1(half2)}
__device__ float2 g_wfrag[27 * 8 * 2 * 32];

extern "C" __global__ void wprep_kernel(const float* __restrict__ wgt) {
    int idx = blockIdx.x * 256 + threadIdx.x;
    if (idx >= 27 * 8 * 2 * 32) return;
    int lane = idx & 31;
    int r    = idx >> 5;
    int ks2  = r & 1;  r >>= 1;
    int gnt  = r & 7;  r >>= 3;
    int tap  = r;
    int g = lane >> 2, t = lane & 3;
    int co = gnt * 8 + g;
    int c0 = ks2 * 16 + 2 * t;
    int c1 = c0 + 8;
    __half2 b0 = __floats2half2_rn(wgt[(co * CI_ + c0)     * 27 + tap],
                                   wgt[(co * CI_ + c0 + 1) * 27 + tap]);
    __half2 b1 = __floats2half2_rn(wgt[(co * CI_ + c1)     * 27 + tap],
                                   wgt[(co * CI_ + c1 + 1) * 27 + tap]);
    float2 v;
    v.x = __uint_as_float(*(uint32_t*)&b0);
    v.y = __uint_as_float(*(uint32_t*)&b1);
    g_wfrag[idx] = v;
}

__device__ __forceinline__ void ldsm_x4(uint32_t& r0, uint32_t& r1,
                                        uint32_t& r2, uint32_t& r3, uint32_t addr) {
    asm volatile("ldmatrix.sync.aligned.m8n8.x4.shared.b16 {%0,%1,%2,%3}, [%4];"
                 : "=r"(r0), "=r"(r1), "=r"(r2), "=r"(r3) : "r"(addr));
}

extern "C" __global__ void __launch_bounds__(512, 2)
conv_mma_kernel(const float* __restrict__ x, const int* __restrict__ mask,
                const float* __restrict__ bias, float* __restrict__ out)
{
    __shared__ uint32_t scratch[SCR_WORDS];   // [s][20] half2 words; epilogue reuse
    __shared__ float bs[CO_];

    const int tid  = threadIdx.x;
    const int w    = tid >> 5;
    const int lane = tid & 31;
    const int g    = lane >> 2;
    const int t    = lane & 3;

    const int pz = blockIdx.y;               // b*96 + d
    const int b = pz / NV, d = pz % NV;
    const int q0   = blockIdx.x * MT;
    const int q_lo = q0 - 99;

    const int warp_m = (w >> 1) * 32;
    const int warp_n = (w & 1) * 32;

    if (tid < CO_) bs[tid] = bias[tid];

    float acc[2][4][4];
    #pragma unroll
    for (int mt = 0; mt < 2; mt++)
        #pragma unroll
        for (int nt = 0; nt < 4; nt++)
            #pragma unroll
            for (int c = 0; c < 4; c++) acc[mt][nt][c] = 0.0f;

    const float2* wbase = g_wfrag + (size_t)(w & 1) * 4 * 64 + lane;

    // per-lane LDSM base (bytes): row = 99 + warp_m + (lane&15); khalf chunk = (lane>>4)*16B
    uint32_t scr_addr;
    asm("{ .reg .u64 tt; cvta.to.shared.u64 tt, %1; cvt.u32.u64 %0, tt; }"
        : "=r"(scr_addr) : "l"(scratch));
    const uint32_t lbase = scr_addr
        + (uint32_t)((99 + warp_m + (lane & 15)) * (S_W * 4))
        + (uint32_t)((lane >> 4) * 16);

    for (int dz = 0; dz < 3; dz++) {
        const int dcur = d + dz - 1;
        const bool dok = ((unsigned)dcur < (unsigned)NV);
        __syncthreads();   // all warps done reading previous dz's scratch

        // ---- fill: kp = tid>>5 (32 thr/kp), s walks (tid&31)+32j, half2 pack ----
        {
            const int kp = tid >> 5;
            int s  = tid & 31;
            int qg = q_lo + s;
            int hh = (qg + 196) / 98 - 2;
            int ww = qg - hh * ROWW;
            const float* xp0 = x + ((size_t)(b * CI_ + 2 * kp) * NV + (dok ? dcur : 0)) * NV2;
            const float* xp1 = xp0 + NV3;
            uint32_t* sp = scratch + kp;
            #pragma unroll 1
            for (; s < S_ROWS; s += 32) {
                float v0 = 0.0f, v1 = 0.0f;
                if (dok && (unsigned)hh < (unsigned)NV && ww < NV) {
                    int o = hh * NV + ww;
                    v0 = xp0[o]; v1 = xp1[o];
                }
                __half2 h = __floats2half2_rn(v0, v1);
                sp[s * S_W] = *(uint32_t*)&h;
                ww += 32;
                if (ww >= ROWW) { ww -= ROWW; hh++; }
            }
        }
        __syncthreads();

        #pragma unroll 1
        for (int kh = 0; kh < 3; kh++) {
            #pragma unroll 1
            for (int kw = 0; kw < 3; kw++) {
                const int tap   = dz * 9 + kh * 3 + kw;
                const int shift = (kh - 1) * ROWW + (kw - 1);
                const uint32_t taddr = lbase + (uint32_t)(shift * (S_W * 4));
                const float2* wf = wbase + (size_t)tap * 512;

                #pragma unroll
                for (int ks2 = 0; ks2 < 2; ks2++) {
                    float2 bf0 = wf[(0 * 2 + ks2) * 32];
                    float2 bf1 = wf[(1 * 2 + ks2) * 32];
                    float2 bf2 = wf[(2 * 2 + ks2) * 32];
                    float2 bf3 = wf[(3 * 2 + ks2) * 32];

                    #pragma unroll
                    for (int mt = 0; mt < 2; mt++) {
                        uint32_t a0, a1, a2, a3;
                        ldsm_x4(a0, a1, a2, a3,
                                taddr + (uint32_t)(mt * 16 * S_W * 4 + ks2 * 32));
                        #pragma unroll
                        for (int nt = 0; nt < 4; nt++) {
                            float2 bv = (nt == 0) ? bf0 : (nt == 1) ? bf1 : (nt == 2) ? bf2 : bf3;
                            asm volatile(
                                "mma.sync.aligned.m16n8k16.row.col.f32.f16.f16.f32 "
                                "{%0,%1,%2,%3}, {%4,%5,%6,%7}, {%8,%9}, {%0,%1,%2,%3};\n"
                                : "+f"(acc[mt][nt][0]), "+f"(acc[mt][nt][1]),
                                  "+f"(acc[mt][nt][2]), "+f"(acc[mt][nt][3])
                                : "r"(a0), "r"(a1), "r"(a2), "r"(a3),
                                  "r"(__float_as_uint(bv.x)),
                                  "r"(__float_as_uint(bv.y)));
                        }
                    }
                }
            }
        }
    }

    // ---- epilogue: two 128-row passes via smem transpose, coalesced stores ----
    float* ep = (float*)scratch;   // [128][66]
    #pragma unroll 1
    for (int pass = 0; pass < 2; pass++) {
        __syncthreads();
        if ((w >> 3) == pass) {
            const int m_loc = (warp_m & 127);
            #pragma unroll
            for (int mt = 0; mt < 2; mt++) {
                #pragma unroll
                for (int nt = 0; nt < 4; nt++) {
                    int m  = m_loc + mt * 16 + g;
                    int co = warp_n + nt * 8 + 2 * t;
                    *(float2*)(ep + m * EP_STR + co) =
                        make_float2(acc[mt][nt][0], acc[mt][nt][1]);
                    *(float2*)(ep + (m + 8) * EP_STR + co) =
                        make_float2(acc[mt][nt][2], acc[mt][nt][3]);
                }
            }
        }
        __syncthreads();

        const int mg0 = pass * 128;
        #pragma unroll
        for (int it = 0; it < 4; it++) {
            int m  = it * 32 + lane;
            int q  = q0 + mg0 + m;
            int hh = q / ROWW;
            int ww = q - hh * ROWW;
            bool ok = (q < PLANE_Q) && (ww < NV);
            int sp  = hh * NV + ww;
            float mval = 0.0f;
            if (ok) mval = (float)mask[(size_t)pz * NV2 + sp];
            #pragma unroll
            for (int j = 0; j < 4; j++) {
                int co = w * 4 + j;
                if (ok)
                    out[((size_t)(b * CO_ + co) * NV + d) * NV2 + sp] =
                        (ep[m * EP_STR + co] + bs[co]) * mval;
            }
        }
    }
}

extern "C" void kernel_launch(void* const* d_in, const int* in_sizes, int n_in,
                              void* d_out, int out_size)
{
    const float* x    = (const float*)d_in[0];
    const int*   mask = (const int*)  d_in[1];
    const float* wgt  = (const float*)d_in[2];
    const float* bias = (const float*)d_in[3];
    float* out = (float*)d_out;

    wprep_kernel<<<(27 * 8 * 2 * 32 + 255) / 256, 256>>>(wgt);

    dim3 grid(NTILES, 2 * NV);   // (37, 192)
    conv_mma_kernel<<<grid, 512>>>(x, mask, bias, out);
}

// round 17
// speedup vs baseline: 2.0743x; 1.0320x over previous
#include <cuda_runtime.h>
#include <cuda_fp16.h>
#include <cstdint>

// SparseConv3d as implicit GEMM via mma.sync fp16 m16n8k16 + ldmatrix A
// + double-buffered plane fill (fill(dz+1) overlaps mma(dz), one barrier/dz).

#define NV      96
#define NV2     (NV*NV)
#define NV3     (NV*NV2)
#define CI_     32
#define CO_     64
#define ROWW    98
#define PLANE_Q (NV*ROWW)        // 9408
#define MT      256
#define NTILES  37
#define S_ROWS  454
#define S_W     20               // words per s-row (16 kp + 4 pad) -> LDSM conflict-free
#define SCR_WORDS (S_ROWS*S_W)   // 9080
#define SCR_BYTES (SCR_WORDS*4)
#define EP_STR  66
#define SMEM_SZ (2*SCR_BYTES)    // 72640

// B fragments: [tap][gnt(8)][ks2(2)][lane(32)] float2 = {b0(half2), b1(half2)}
__device__ float2 g_wfrag[27 * 8 * 2 * 32];

extern "C" __global__ void wprep_kernel(const float* __restrict__ wgt) {
    int idx = blockIdx.x * 256 + threadIdx.x;
    if (idx >= 27 * 8 * 2 * 32) return;
    int lane = idx & 31;
    int r    = idx >> 5;
    int ks2  = r & 1;  r >>= 1;
    int gnt  = r & 7;  r >>= 3;
    int tap  = r;
    int g = lane >> 2, t = lane & 3;
    int co = gnt * 8 + g;
    int c0 = ks2 * 16 + 2 * t;
    int c1 = c0 + 8;
    __half2 b0 = __floats2half2_rn(wgt[(co * CI_ + c0)     * 27 + tap],
                                   wgt[(co * CI_ + c0 + 1) * 27 + tap]);
    __half2 b1 = __floats2half2_rn(wgt[(co * CI_ + c1)     * 27 + tap],
                                   wgt[(co * CI_ + c1 + 1) * 27 + tap]);
    float2 v;
    v.x = __uint_as_float(*(uint32_t*)&b0);
    v.y = __uint_as_float(*(uint32_t*)&b1);
    g_wfrag[idx] = v;
}

__device__ __forceinline__ void ldsm_x4(uint32_t& r0, uint32_t& r1,
                                        uint32_t& r2, uint32_t& r3, uint32_t addr) {
    asm volatile("ldmatrix.sync.aligned.m8n8.x4.shared.b16 {%0,%1,%2,%3}, [%4];"
                 : "=r"(r0), "=r"(r1), "=r"(r2), "=r"(r3) : "r"(addr));
}

extern "C" __global__ void __launch_bounds__(512, 2)
conv_mma_kernel(const float* __restrict__ x, const int* __restrict__ mask,
                const float* __restrict__ bias, float* __restrict__ out)
{
    extern __shared__ uint32_t scratch[];    // 2 x [s][20] half2 words
    __shared__ float bs[CO_];

    const int tid  = threadIdx.x;
    const int w    = tid >> 5;
    const int lane = tid & 31;
    const int g    = lane >> 2;
    const int t    = lane & 3;

    const int pz = blockIdx.y;               // b*96 + d
    const int b = pz / NV, d = pz % NV;
    const int q0   = blockIdx.x * MT;
    const int q_lo = q0 - 99;

    const int warp_m = (w >> 1) * 32;
    const int warp_n = (w & 1) * 32;

    if (tid < CO_) bs[tid] = bias[tid];

    float acc[2][4][4];
    #pragma unroll
    for (int mt = 0; mt < 2; mt++)
        #pragma unroll
        for (int nt = 0; nt < 4; nt++)
            #pragma unroll
            for (int c = 0; c < 4; c++) acc[mt][nt][c] = 0.0f;

    const float2* wbase = g_wfrag + (size_t)(w & 1) * 4 * 64 + lane;

    uint32_t scr_addr;
    asm("{ .reg .u64 tt; cvta.to.shared.u64 tt, %1; cvt.u32.u64 %0, tt; }"
        : "=r"(scr_addr) : "l"(scratch));
    const uint32_t lbase = scr_addr
        + (uint32_t)((99 + warp_m + (lane & 15)) * (S_W * 4))
        + (uint32_t)((lane >> 4) * 16);

    // fill lambda: plane dcur -> buffer p
    const int fill_kp = tid >> 5;
    const int fill_s0 = tid & 31;
    auto fill_plane = [&](int dcur, int p) {
        const bool dok = ((unsigned)dcur < (unsigned)NV);
        int s  = fill_s0;
        int qg = q_lo + s;
        int hh = (qg + 196) / 98 - 2;
        int ww = qg - hh * ROWW;
        const float* xp0 = x + ((size_t)(b * CI_ + 2 * fill_kp) * NV + (dok ? dcur : 0)) * NV2;
        const float* xp1 = xp0 + NV3;
        uint32_t* sp = scratch + p * SCR_WORDS + fill_kp;
        #pragma unroll 1
        for (; s < S_ROWS; s += 32) {
            float v0 = 0.0f, v1 = 0.0f;
            if (dok && (unsigned)hh < (unsigned)NV && ww < NV) {
                int o = hh * NV + ww;
                v0 = xp0[o]; v1 = xp1[o];
            }
            __half2 h = __floats2half2_rn(v0, v1);
            sp[s * S_W] = *(uint32_t*)&h;
            ww += 32;
            if (ww >= ROWW) { ww -= ROWW; hh++; }
        }
    };

    fill_plane(d - 1, 0);
    __syncthreads();

    for (int dz = 0; dz < 3; dz++) {
        // overlap: fill next plane into the other buffer while doing mma on this one
        if (dz < 2) fill_plane(d + dz, (dz + 1) & 1);

        const uint32_t buf_off = (uint32_t)((dz & 1) * SCR_BYTES);
        #pragma unroll 1
        for (int kh = 0; kh < 3; kh++) {
            #pragma unroll 1
            for (int kw = 0; kw < 3; kw++) {
                const int tap   = dz * 9 + kh * 3 + kw;
                const int shift = (kh - 1) * ROWW + (kw - 1);
                const uint32_t taddr = lbase + buf_off + (uint32_t)(shift * (S_W * 4));
                const float2* wf = wbase + (size_t)tap * 512;

                #pragma unroll
                for (int ks2 = 0; ks2 < 2; ks2++) {
                    float2 bf0 = wf[(0 * 2 + ks2) * 32];
                    float2 bf1 = wf[(1 * 2 + ks2) * 32];
                    float2 bf2 = wf[(2 * 2 + ks2) * 32];
                    float2 bf3 = wf[(3 * 2 + ks2) * 32];

                    #pragma unroll
                    for (int mt = 0; mt < 2; mt++) {
                        uint32_t a0, a1, a2, a3;
                        ldsm_x4(a0, a1, a2, a3,
                                taddr + (uint32_t)(mt * 16 * S_W * 4 + ks2 * 32));
                        #pragma unroll
                        for (int nt = 0; nt < 4; nt++) {
                            float2 bv = (nt == 0) ? bf0 : (nt == 1) ? bf1 : (nt == 2) ? bf2 : bf3;
                            asm volatile(
                                "mma.sync.aligned.m16n8k16.row.col.f32.f16.f16.f32 "
                                "{%0,%1,%2,%3}, {%4,%5,%6,%7}, {%8,%9}, {%0,%1,%2,%3};\n"
                                : "+f"(acc[mt][nt][0]), "+f"(acc[mt][nt][1]),
                                  "+f"(acc[mt][nt][2]), "+f"(acc[mt][nt][3])
                                : "r"(a0), "r"(a1), "r"(a2), "r"(a3),
                                  "r"(__float_as_uint(bv.x)),
                                  "r"(__float_as_uint(bv.y)));
                        }
                    }
                }
            }
        }
        __syncthreads();   // fill(dz+1) visible; buffer (dz&1) free for reuse
    }

    // ---- epilogue: two 128-row passes via smem transpose, coalesced stores ----
    float* ep = (float*)scratch;   // [128][66] in buf0
    #pragma unroll 1
    for (int pass = 0; pass < 2; pass++) {
        __syncthreads();
        if ((w >> 3) == pass) {
            const int m_loc = (warp_m & 127);
            #pragma unroll
            for (int mt = 0; mt < 2; mt++) {
                #pragma unroll
                for (int nt = 0; nt < 4; nt++) {
                    int m  = m_loc + mt * 16 + g;
                    int co = warp_n + nt * 8 + 2 * t;
                    *(float2*)(ep + m * EP_STR + co) =
                        make_float2(acc[mt][nt][0], acc[mt][nt][1]);
                    *(float2*)(ep + (m + 8) * EP_STR + co) =
                        make_float2(acc[mt][nt][2], acc[mt][nt][3]);
                }
            }
        }
        __syncthreads();

        const int mg0 = pass * 128;
        #pragma unroll
        for (int it = 0; it < 4; it++) {
            int m  = it * 32 + lane;
            int q  = q0 + mg0 + m;
            int hh = q / ROWW;
            int ww = q - hh * ROWW;
            bool ok = (q < PLANE_Q) && (ww < NV);
            int sp  = hh * NV + ww;
            float mval = 0.0f;
            if (ok) mval = (float)mask[(size_t)pz * NV2 + sp];
            #pragma unroll
            for (int j = 0; j < 4; j++) {
                int co = w * 4 + j;
                if (ok)
                    out[((size_t)(b * CO_ + co) * NV + d) * NV2 + sp] =
                        (ep[m * EP_STR + co] + bs[co]) * mval;
            }
        }
    }
}

extern "C" void kernel_launch(void* const* d_in, const int* in_sizes, int n_in,
                              void* d_out, int out_size)
{
    const float* x    = (const float*)d_in[0];
    const int*   mask = (const int*)  d_in[1];
    const float* wgt  = (const float*)d_in[2];
    const float* bias = (const float*)d_in[3];
    float* out = (float*)d_out;

    cudaFuncSetAttribute(conv_mma_kernel,
                         cudaFuncAttributeMaxDynamicSharedMemorySize, SMEM_SZ);

    wprep_kernel<<<(27 * 8 * 2 * 32 + 255) / 256, 256>>>(wgt);

    dim3 grid(NTILES, 2 * NV);   // (37, 192)
    conv_mma_kernel<<<grid, 512, SMEM_SZ>>>(x, mask, bias, out);
}